// round 1
// baseline (speedup 1.0000x reference)
#include <cuda_runtime.h>
#include <math.h>

#define NN 20000
#define EE 320000
#define HID 256

// ---------------- scratch (static device allocations) ----------------
__device__ float g_deg[NN];
__device__ float g_norm[EE];
__device__ int   g_cnt[NN];
__device__ int   g_rowptr[NN + 1];
__device__ int   g_fill[NN];
__device__ int   g_csrc[EE];
__device__ float g_cval[EE];
__device__ float g_Lx[(size_t)NN * HID];
__device__ float g_Lh[(size_t)NN * HID];
__device__ float g_Lhr[(size_t)NN * HID];
__device__ float g_Z[(size_t)NN * HID];
__device__ float g_hr[(size_t)NN * HID];
__device__ float g_XH[(size_t)NN * HID];
__device__ float g_B1[1024 * 768];
__device__ float g_bias1[768];
__device__ float g_B2[512 * 256];

// ---------------- graph preprocessing ----------------
__global__ void zero_kernel(int n) {
    int i = blockIdx.x * blockDim.x + threadIdx.x;
    if (i < n) { g_deg[i] = 0.f; g_cnt[i] = 0; }
}

__global__ void deg_kernel(const int* __restrict__ ei, const float* __restrict__ ew, int E) {
    int e = blockIdx.x * blockDim.x + threadIdx.x;
    if (e < E) atomicAdd(&g_deg[ei[e]], ew[e]);
}

__global__ void norm_count_kernel(const int* __restrict__ ei, const float* __restrict__ ew, int E) {
    int e = blockIdx.x * blockDim.x + threadIdx.x;
    if (e < E) {
        int s = ei[e], d = ei[E + e];
        float ds = g_deg[s], dd = g_deg[d];
        float is = ds > 0.f ? rsqrtf(ds) : 0.f;
        float id = dd > 0.f ? rsqrtf(dd) : 0.f;
        g_norm[e] = -is * ew[e] * id;
        atomicAdd(&g_cnt[d], 1);
    }
}

// single-block exclusive scan over g_cnt -> g_rowptr, g_fill
__global__ void scan_kernel(int n) {
    __shared__ int sh[1024];
    int t = threadIdx.x;
    int chunk = (n + 1023) >> 10;
    int base = t * chunk;
    int end = min(base + chunk, n);
    int s = 0;
    for (int i = base; i < end; i++) s += g_cnt[i];
    sh[t] = s;
    __syncthreads();
    for (int off = 1; off < 1024; off <<= 1) {
        int v = (t >= off) ? sh[t - off] : 0;
        __syncthreads();
        sh[t] += v;
        __syncthreads();
    }
    int run = sh[t] - s;  // exclusive prefix for this thread's chunk
    for (int i = base; i < end; i++) {
        g_rowptr[i] = run;
        g_fill[i]   = run;
        run += g_cnt[i];
    }
    if (t == 1023) g_rowptr[n] = sh[1023];
}

__global__ void scatter_kernel(const int* __restrict__ ei, int E) {
    int e = blockIdx.x * blockDim.x + threadIdx.x;
    if (e < E) {
        int d = ei[E + e];
        int p = atomicAdd(&g_fill[d], 1);
        g_csrc[p] = ei[e];
        g_cval[p] = g_norm[e];
    }
}

// ---------------- SpMM: Lx = L@x, Lh = L@h (one block of 128 per node) ----------------
__global__ void lap_dual_kernel(const float* __restrict__ x, const float* __restrict__ h) {
    int node = blockIdx.x;
    int t = threadIdx.x;
    const float* src = (t < 64) ? x : h;
    float* dst = (t < 64) ? g_Lx : g_Lh;
    int c = (t & 63) << 2;
    float4 acc = make_float4(0.f, 0.f, 0.f, 0.f);
    int e1 = g_rowptr[node + 1];
    for (int e = g_rowptr[node]; e < e1; e++) {
        int s = g_csrc[e];
        float v = g_cval[e];
        float4 xv = *(const float4*)(src + (size_t)s * HID + c);
        acc.x += v * xv.x; acc.y += v * xv.y; acc.z += v * xv.z; acc.w += v * xv.w;
    }
    *(float4*)(dst + (size_t)node * HID + c) = acc;
}

// Lhr = L @ hr (64 threads per node)
__global__ void lap_single_kernel() {
    int node = blockIdx.x;
    int t = threadIdx.x;
    int c = t << 2;
    float4 acc = make_float4(0.f, 0.f, 0.f, 0.f);
    int e1 = g_rowptr[node + 1];
    for (int e = g_rowptr[node]; e < e1; e++) {
        int s = g_csrc[e];
        float v = g_cval[e];
        float4 xv = *(const float4*)(g_hr + (size_t)s * HID + c);
        acc.x += v * xv.x; acc.y += v * xv.y; acc.z += v * xv.z; acc.w += v * xv.w;
    }
    *(float4*)(g_Lhr + (size_t)node * HID + c) = acc;
}

// ---------------- weight packing ----------------
// B1[1024][768]: rows 0-255 x-part, 256-511 Lx-part, 512-767 h-part, 768-1023 Lh-part
// cols 0-255 z-gate, 256-511 r-gate, 512-767 xh-gate (h/Lh parts zero for xh)
__global__ void pack1_kernel(const float* __restrict__ Wxz, const float* __restrict__ Whz,
                             const float* __restrict__ Wxr, const float* __restrict__ Whr,
                             const float* __restrict__ Wxh,
                             const float* __restrict__ bxz, const float* __restrict__ bhz,
                             const float* __restrict__ bxr, const float* __restrict__ bhr,
                             const float* __restrict__ bxh) {
    int idx = blockIdx.x * blockDim.x + threadIdx.x;
    if (idx < 1024 * 768) {
        int r = idx / 768, c = idx % 768;
        int part = r >> 8, k = r & 255, gate = c >> 8, j = c & 255;
        int off = (part & 1) * 65536 + k * 256 + j;  // W[t][k][j], t = part&1
        float v = 0.f;
        if (part < 2) {
            const float* W = (gate == 0) ? Wxz : (gate == 1) ? Wxr : Wxh;
            v = W[off];
        } else if (gate < 2) {
            const float* W = (gate == 0) ? Whz : Whr;
            v = W[off];
        }
        g_B1[idx] = v;
    }
    if (idx < 768) {
        int gate = idx >> 8, j = idx & 255;
        g_bias1[idx] = (gate == 0) ? bxz[j] + bhz[j]
                     : (gate == 1) ? bxr[j] + bhr[j]
                                   : bxh[j];
    }
}

// B2[512][256]: rows 0-255 = Whh[0], 256-511 = Whh[1]
__global__ void pack2_kernel(const float* __restrict__ Whh) {
    int idx = blockIdx.x * blockDim.x + threadIdx.x;
    if (idx < 512 * 256) {
        int r = idx / 256, c = idx % 256;
        g_B2[idx] = Whh[(r >> 8) * 65536 + (r & 255) * 256 + c];
    }
}

// ---------------- fused SGEMM + epilogues ----------------
// C[M,NC] = concat(A0..A{NPARTS-1})[M, NPARTS*256] @ B[NPARTS*256, NC]
// EPI 0: gate epilogue (writes g_Z / g_hr / g_XH), EPI 1: GRU epilogue (writes h0),
// EPI 2: plain + bias (final linear out).
__device__ __forceinline__ float sigmoidf_(float v) { return 1.f / (1.f + expf(-v)); }

#define BM 128
#define BN 128
#define BK 8

template <int NPARTS, int EPI, bool RELUA>
__global__ __launch_bounds__(256, 2) void gemm_kernel(
    const float* __restrict__ A0, const float* __restrict__ A1,
    const float* __restrict__ A2, const float* __restrict__ A3,
    const float* __restrict__ B, const float* __restrict__ bias,
    int M, int NC, const float* __restrict__ haux, float* __restrict__ dout) {
    __shared__ float As[BK][BM + 4];
    __shared__ float Bs[BK][BN];

    int tid = threadIdx.x;
    int col0 = blockIdx.x * BN;
    int row0 = blockIdx.y * BM;
    int tx = tid & 15, ty = tid >> 4;

    int arow = tid >> 1;          // 0..127
    int acol = (tid & 1) << 2;    // 0 or 4
    int brow = tid >> 5;          // 0..7
    int bcol = (tid & 31) << 2;   // 0..124

    float acc[8][8];
#pragma unroll
    for (int i = 0; i < 8; i++)
#pragma unroll
        for (int j = 0; j < 8; j++) acc[i][j] = 0.f;

    int grow = row0 + arow;
    bool arow_ok = (grow < M);

#pragma unroll
    for (int part = 0; part < NPARTS; part++) {
        const float* Ap = (part == 0) ? A0 : (part == 1) ? A1 : (part == 2) ? A2 : A3;
        for (int kb = 0; kb < 256; kb += BK) {
            // load A tile (BM x BK), transposed into shared
            float4 av = make_float4(0.f, 0.f, 0.f, 0.f);
            if (arow_ok) {
                av = *(const float4*)(Ap + (size_t)grow * 256 + kb + acol);
                if (RELUA) {
                    av.x = fmaxf(av.x, 0.f); av.y = fmaxf(av.y, 0.f);
                    av.z = fmaxf(av.z, 0.f); av.w = fmaxf(av.w, 0.f);
                }
            }
            As[acol + 0][arow] = av.x;
            As[acol + 1][arow] = av.y;
            As[acol + 2][arow] = av.z;
            As[acol + 3][arow] = av.w;
            // load B tile (BK x BN)
            int kt = part * 256 + kb;
            float4 bv = *(const float4*)(B + (size_t)(kt + brow) * NC + col0 + bcol);
            *(float4*)&Bs[brow][bcol] = bv;
            __syncthreads();
#pragma unroll
            for (int k = 0; k < BK; k++) {
                float ra[8], rb[8];
#pragma unroll
                for (int i = 0; i < 8; i++) ra[i] = As[k][ty * 8 + i];
#pragma unroll
                for (int j = 0; j < 8; j++) rb[j] = Bs[k][tx * 8 + j];
#pragma unroll
                for (int i = 0; i < 8; i++)
#pragma unroll
                    for (int j = 0; j < 8; j++) acc[i][j] += ra[i] * rb[j];
            }
            __syncthreads();
        }
    }

    // epilogue
#pragma unroll
    for (int i = 0; i < 8; i++) {
        int row = row0 + ty * 8 + i;
        if (row >= M) continue;
#pragma unroll
        for (int j = 0; j < 8; j++) {
            int c = col0 + tx * 8 + j;
            float v = acc[i][j] + bias[c];
            if (EPI == 0) {
                int gate = c >> 8;
                int jj = c & 255;
                size_t o = (size_t)row * 256 + jj;
                if (gate == 0) {
                    g_Z[o] = sigmoidf_(v);
                } else if (gate == 1) {
                    g_hr[o] = haux[o] * sigmoidf_(v);
                } else {
                    g_XH[o] = v;
                }
            } else if (EPI == 1) {
                size_t o = (size_t)row * 256 + c;
                float ht = tanhf(g_XH[o] + v);
                float z = g_Z[o];
                dout[o] = z * haux[o] + (1.f - z) * ht;
            } else {
                dout[(size_t)row * NC + c] = v;
            }
        }
    }
}

// ---------------- host launch ----------------
extern "C" void kernel_launch(void* const* d_in, const int* in_sizes, int n_in,
                              void* d_out, int out_size) {
    const float* x   = (const float*)d_in[0];
    const float* h   = (const float*)d_in[1];
    const int*   ei  = (const int*)d_in[2];
    const float* ew  = (const float*)d_in[3];
    const float* Wxz = (const float*)d_in[4];
    const float* bxz = (const float*)d_in[5];
    const float* Whz = (const float*)d_in[6];
    const float* bhz = (const float*)d_in[7];
    const float* Wxr = (const float*)d_in[8];
    const float* bxr = (const float*)d_in[9];
    const float* Whr = (const float*)d_in[10];
    const float* bhr = (const float*)d_in[11];
    const float* Wxh = (const float*)d_in[12];
    const float* bxh = (const float*)d_in[13];
    const float* Whh = (const float*)d_in[14];
    const float* bhh = (const float*)d_in[15];
    const float* Wl  = (const float*)d_in[16];
    const float* bl  = (const float*)d_in[17];

    int M = in_sizes[0] / HID;   // 20000
    int E = in_sizes[3];         // 320000

    float* outp = (float*)d_out;                   // [M,128]
    float* h0   = outp + (size_t)M * 128;          // [M,256]

    void *pLx, *pLh, *pLhr, *pHr, *pB1, *pb1, *pB2;
    cudaGetSymbolAddress(&pLx, g_Lx);
    cudaGetSymbolAddress(&pLh, g_Lh);
    cudaGetSymbolAddress(&pLhr, g_Lhr);
    cudaGetSymbolAddress(&pHr, g_hr);
    cudaGetSymbolAddress(&pB1, g_B1);
    cudaGetSymbolAddress(&pb1, g_bias1);
    cudaGetSymbolAddress(&pB2, g_B2);

    int eb = (E + 255) / 256;
    int nb = (M + 255) / 256;
    int rb = (M + BM - 1) / BM;

    // graph preprocessing (CSR by dst)
    zero_kernel<<<nb, 256>>>(M);
    deg_kernel<<<eb, 256>>>(ei, ew, E);
    norm_count_kernel<<<eb, 256>>>(ei, ew, E);
    scan_kernel<<<1, 1024>>>(M);
    scatter_kernel<<<eb, 256>>>(ei, E);

    // weight packing (independent of graph work)
    pack1_kernel<<<(1024 * 768 + 255) / 256, 256>>>(Wxz, Whz, Wxr, Whr, Wxh,
                                                    bxz, bhz, bxr, bhr, bxh);
    pack2_kernel<<<(512 * 256 + 255) / 256, 256>>>(Whh);

    // Lx, Lh
    lap_dual_kernel<<<M, 128>>>(x, h);

    // GEMM1: [x|Lx|h|Lh] @ B1 -> Z, hr, XH (fused gates)
    gemm_kernel<4, 0, false><<<dim3(6, rb), 256>>>(
        x, (const float*)pLx, h, (const float*)pLh,
        (const float*)pB1, (const float*)pb1, M, 768, h, nullptr);

    // Lhr = L @ hr
    lap_single_kernel<<<M, 64>>>();

    // GEMM2: [hr|Lhr] @ B2 -> h0 (fused tanh + GRU blend), written to d_out
    gemm_kernel<2, 1, false><<<dim3(2, rb), 256>>>(
        (const float*)pHr, (const float*)pLhr, nullptr, nullptr,
        (const float*)pB2, bhh, M, 256, h, h0);

    // GEMM3: relu(h0) @ Wl + bl -> out
    gemm_kernel<1, 2, true><<<dim3(1, rb), 256>>>(
        h0, nullptr, nullptr, nullptr,
        Wl, bl, M, 128, nullptr, outp);
}

// round 4
// speedup vs baseline: 2.4131x; 2.4131x over previous
#include <cuda_runtime.h>
#include <math.h>
#include <stdint.h>

#define NN 20000
#define EE 320000
#define HID 256
#define BM 128
#define BN 128

// ---------------- scratch (static device allocations) ----------------
__device__ float g_deg[NN];
__device__ float g_norm[EE];
__device__ int   g_cnt[NN];
__device__ int   g_rowptr[NN + 1];
__device__ int   g_fill[NN];
__device__ int   g_csrc[EE];
__device__ float g_cval[EE];
__device__ __align__(16) float g_Lx[(size_t)NN * HID];
__device__ __align__(16) float g_Lh[(size_t)NN * HID];
__device__ __align__(16) float g_Lhr[(size_t)NN * HID];
__device__ __align__(16) float g_Z[(size_t)NN * HID];
__device__ __align__(16) float g_hr[(size_t)NN * HID];
__device__ __align__(16) float g_XH[(size_t)NN * HID];
__device__ __align__(16) uint32_t g_B1T[768 * 1024];   // [n][k] tf32, packed K
__device__ float g_bias1[768];
__device__ __align__(16) uint32_t g_B2T[256 * 512];    // [n][k] tf32
__device__ __align__(16) uint32_t g_WlT[128 * 256];    // [n][k] tf32

__device__ __forceinline__ uint32_t f2tf(float f) {
    uint32_t r;
    asm("cvt.rna.tf32.f32 %0, %1;" : "=r"(r) : "f"(f));
    return r;
}

// ---------------- graph preprocessing ----------------
__global__ void zero_kernel(int n) {
    int i = blockIdx.x * blockDim.x + threadIdx.x;
    if (i < n) { g_deg[i] = 0.f; g_cnt[i] = 0; }
}
__global__ void deg_kernel(const int* __restrict__ ei, const float* __restrict__ ew, int E) {
    int e = blockIdx.x * blockDim.x + threadIdx.x;
    if (e < E) atomicAdd(&g_deg[ei[e]], ew[e]);
}
__global__ void norm_count_kernel(const int* __restrict__ ei, const float* __restrict__ ew, int E) {
    int e = blockIdx.x * blockDim.x + threadIdx.x;
    if (e < E) {
        int s = ei[e], d = ei[E + e];
        float ds = g_deg[s], dd = g_deg[d];
        float is = ds > 0.f ? rsqrtf(ds) : 0.f;
        float id = dd > 0.f ? rsqrtf(dd) : 0.f;
        g_norm[e] = -is * ew[e] * id;
        atomicAdd(&g_cnt[d], 1);
    }
}
__global__ void scan_kernel(int n) {
    __shared__ int sh[1024];
    int t = threadIdx.x;
    int chunk = (n + 1023) >> 10;
    int base = t * chunk;
    int end = min(base + chunk, n);
    int s = 0;
    for (int i = base; i < end; i++) s += g_cnt[i];
    sh[t] = s;
    __syncthreads();
    for (int off = 1; off < 1024; off <<= 1) {
        int v = (t >= off) ? sh[t - off] : 0;
        __syncthreads();
        sh[t] += v;
        __syncthreads();
    }
    int run = sh[t] - s;
    for (int i = base; i < end; i++) {
        g_rowptr[i] = run;
        g_fill[i]   = run;
        run += g_cnt[i];
    }
    if (t == 1023) g_rowptr[n] = sh[1023];
}
__global__ void scatter_kernel(const int* __restrict__ ei, int E) {
    int e = blockIdx.x * blockDim.x + threadIdx.x;
    if (e < E) {
        int d = ei[E + e];
        int p = atomicAdd(&g_fill[d], 1);
        g_csrc[p] = ei[e];
        g_cval[p] = g_norm[e];
    }
}

// ---------------- SpMM ----------------
__global__ void lap_dual_kernel(const float* __restrict__ x, const float* __restrict__ h) {
    int node = blockIdx.x;
    int t = threadIdx.x;
    const float* src = (t < 64) ? x : h;
    float* dst = (t < 64) ? g_Lx : g_Lh;
    int c = (t & 63) << 2;
    float4 acc = make_float4(0.f, 0.f, 0.f, 0.f);
    int e1 = g_rowptr[node + 1];
    for (int e = g_rowptr[node]; e < e1; e++) {
        int s = g_csrc[e];
        float v = g_cval[e];
        float4 xv = *(const float4*)(src + (size_t)s * HID + c);
        acc.x += v * xv.x; acc.y += v * xv.y; acc.z += v * xv.z; acc.w += v * xv.w;
    }
    *(float4*)(dst + (size_t)node * HID + c) = acc;
}
__global__ void lap_single_kernel() {
    int node = blockIdx.x;
    int t = threadIdx.x;
    int c = t << 2;
    float4 acc = make_float4(0.f, 0.f, 0.f, 0.f);
    int e1 = g_rowptr[node + 1];
    for (int e = g_rowptr[node]; e < e1; e++) {
        int s = g_csrc[e];
        float v = g_cval[e];
        float4 xv = *(const float4*)(g_hr + (size_t)s * HID + c);
        acc.x += v * xv.x; acc.y += v * xv.y; acc.z += v * xv.z; acc.w += v * xv.w;
    }
    *(float4*)(g_Lhr + (size_t)node * HID + c) = acc;
}

// ---------------- weight packing (transposed [N][K], tf32) ----------------
__global__ void pack1_kernel(const float* __restrict__ Wxz, const float* __restrict__ Whz,
                             const float* __restrict__ Wxr, const float* __restrict__ Whr,
                             const float* __restrict__ Wxh,
                             const float* __restrict__ bxz, const float* __restrict__ bhz,
                             const float* __restrict__ bxr, const float* __restrict__ bhr,
                             const float* __restrict__ bxh) {
    int idx = blockIdx.x * blockDim.x + threadIdx.x;
    if (idx < 768 * 1024) {
        int n = idx >> 10, r = idx & 1023;
        int part = r >> 8, k = r & 255, gate = n >> 8, j = n & 255;
        int off = (part & 1) * 65536 + k * 256 + j;
        float v = 0.f;
        if (part < 2) {
            const float* W = (gate == 0) ? Wxz : (gate == 1) ? Wxr : Wxh;
            v = W[off];
        } else if (gate < 2) {
            const float* W = (gate == 0) ? Whz : Whr;
            v = W[off];
        }
        g_B1T[idx] = f2tf(v);
    }
    if (idx < 768) {
        int gate = idx >> 8, j = idx & 255;
        g_bias1[idx] = (gate == 0) ? bxz[j] + bhz[j]
                     : (gate == 1) ? bxr[j] + bhr[j]
                                   : bxh[j];
    }
}
__global__ void pack2_kernel(const float* __restrict__ Whh) {
    int idx = blockIdx.x * blockDim.x + threadIdx.x;
    if (idx < 256 * 512) {
        int n = idx >> 9, r = idx & 511;
        g_B2T[idx] = f2tf(Whh[(r >> 8) * 65536 + (r & 255) * 256 + n]);
    }
}
__global__ void pack3_kernel(const float* __restrict__ Wl) {
    int idx = blockIdx.x * blockDim.x + threadIdx.x;
    if (idx < 128 * 256) {
        int n = idx >> 8, k = idx & 255;
        g_WlT[idx] = f2tf(Wl[k * 128 + n]);
    }
}

// ---------------- tf32 mma.sync GEMM ----------------
// C[M, NC] = concat(A parts)[M, NPARTS*256] @ B^T (BT is [NC][NPARTS*256] tf32)
// 8 warps as 4(m) x 2(n); warp tile 32x64; m16n8k8 tf32 MMAs; BK=32.
#define MMA_TF32(c, a0, a1, a2, a3, b0, b1) \
    asm volatile("mma.sync.aligned.m16n8k8.row.col.f32.tf32.tf32.f32 " \
        "{%0,%1,%2,%3}, {%4,%5,%6,%7}, {%8,%9}, {%0,%1,%2,%3};" \
        : "+f"((c)[0]), "+f"((c)[1]), "+f"((c)[2]), "+f"((c)[3]) \
        : "r"(a0), "r"(a1), "r"(a2), "r"(a3), "r"(b0), "r"(b1))

#define LDA 36   // padded stride (floats); 36*4=144 bytes keeps 16B alignment

__device__ __forceinline__ float sigmoidf_(float v) { return 1.f / (1.f + expf(-v)); }

template <int NPARTS, int EPI, bool RELUA>
__global__ __launch_bounds__(256, 2)
void mm_gemm(const float* __restrict__ A0, const float* __restrict__ A1,
             const float* __restrict__ A2, const float* __restrict__ A3,
             const uint32_t* __restrict__ BT, const float* __restrict__ bias,
             int M, int NC, const float* __restrict__ haux, float* __restrict__ dout) {
    constexpr int KT  = NPARTS * 256;
    constexpr int NCH = NPARTS * 8;   // k-chunks of 32
    __shared__ uint32_t As[BM * LDA];
    __shared__ uint32_t Bs[BN * LDA];

    int tid = threadIdx.x;
    int wid = tid >> 5, lane = tid & 31;
    int g = lane >> 2, tg = lane & 3;
    int m_off = (wid >> 1) * 32;
    int n_off = (wid & 1) * 64;
    int col0 = blockIdx.x * BN, row0 = blockIdx.y * BM;

    // per-thread tile-load coords: 4 x uint4 per tile (128 x 32 elems)
    int lr[4], lc[4];
#pragma unroll
    for (int i = 0; i < 4; i++) {
        int q = tid + 256 * i;
        lr[i] = q >> 3;          // 0..127
        lc[i] = (q & 7) << 2;    // 0,4,..,28
    }

    float acc[2][8][4];
#pragma unroll
    for (int t = 0; t < 2; t++)
#pragma unroll
        for (int j = 0; j < 8; j++)
#pragma unroll
            for (int q = 0; q < 4; q++) acc[t][j][q] = 0.f;

    uint4 sa[4], sb[4];

    // ---- load chunk 0 into registers ----
    {
        const float* Ap = A0;
        int koff = 0;
#pragma unroll
        for (int i = 0; i < 4; i++) {
            int gr = row0 + lr[i];
            float4 v = make_float4(0.f, 0.f, 0.f, 0.f);
            if (gr < M) v = *(const float4*)(Ap + (size_t)gr * 256 + koff + lc[i]);
            if (RELUA) {
                v.x = fmaxf(v.x, 0.f); v.y = fmaxf(v.y, 0.f);
                v.z = fmaxf(v.z, 0.f); v.w = fmaxf(v.w, 0.f);
            }
            sa[i] = make_uint4(f2tf(v.x), f2tf(v.y), f2tf(v.z), f2tf(v.w));
            int gn = col0 + lr[i];
            sb[i] = *(const uint4*)(BT + (size_t)gn * KT + lc[i]);
        }
    }

    for (int c = 0; c < NCH; c++) {
        if (c > 0) __syncthreads();   // protect prior chunk's shared reads
#pragma unroll
        for (int i = 0; i < 4; i++) {
            *(uint4*)&As[lr[i] * LDA + lc[i]] = sa[i];
            *(uint4*)&Bs[lr[i] * LDA + lc[i]] = sb[i];
        }
        __syncthreads();

        // prefetch next chunk
        if (c + 1 < NCH) {
            int cn = c + 1;
            const float* Ap;
            if (NPARTS == 1) Ap = A0;
            else {
                int part = cn >> 3;
                Ap = (part == 0) ? A0 : (part == 1) ? A1 : (part == 2) ? A2 : A3;
            }
            int koff = (cn & 7) * 32;
            int kg = cn * 32;
#pragma unroll
            for (int i = 0; i < 4; i++) {
                int gr = row0 + lr[i];
                float4 v = make_float4(0.f, 0.f, 0.f, 0.f);
                if (gr < M) v = *(const float4*)(Ap + (size_t)gr * 256 + koff + lc[i]);
                if (RELUA) {
                    v.x = fmaxf(v.x, 0.f); v.y = fmaxf(v.y, 0.f);
                    v.z = fmaxf(v.z, 0.f); v.w = fmaxf(v.w, 0.f);
                }
                sa[i] = make_uint4(f2tf(v.x), f2tf(v.y), f2tf(v.z), f2tf(v.w));
                int gn = col0 + lr[i];
                sb[i] = *(const uint4*)(BT + (size_t)gn * KT + kg + lc[i]);
            }
        }

        // MMA over 4 k-steps of 8
#pragma unroll
        for (int ks = 0; ks < 4; ks++) {
            int k0 = ks * 8;
            uint32_t af[2][4];
#pragma unroll
            for (int t = 0; t < 2; t++) {
                int r0 = m_off + 16 * t + g;
                af[t][0] = As[r0 * LDA + k0 + tg];
                af[t][1] = As[(r0 + 8) * LDA + k0 + tg];
                af[t][2] = As[r0 * LDA + k0 + 4 + tg];
                af[t][3] = As[(r0 + 8) * LDA + k0 + 4 + tg];
            }
#pragma unroll
            for (int j = 0; j < 8; j++) {
                int n = n_off + 8 * j + g;
                uint32_t b0 = Bs[n * LDA + k0 + tg];
                uint32_t b1 = Bs[n * LDA + k0 + 4 + tg];
                MMA_TF32(acc[0][j], af[0][0], af[0][1], af[0][2], af[0][3], b0, b1);
                MMA_TF32(acc[1][j], af[1][0], af[1][1], af[1][2], af[1][3], b0, b1);
            }
        }
    }

    // ---- epilogue ----
#pragma unroll
    for (int t = 0; t < 2; t++) {
#pragma unroll
        for (int j = 0; j < 8; j++) {
#pragma unroll
            for (int q = 0; q < 4; q++) {
                int row = row0 + m_off + 16 * t + g + ((q >= 2) ? 8 : 0);
                int cc  = col0 + n_off + 8 * j + 2 * tg + (q & 1);
                if (row >= M) continue;
                float v = acc[t][j][q] + bias[cc];
                if (EPI == 0) {
                    int gate = cc >> 8, jj = cc & 255;
                    size_t o = (size_t)row * 256 + jj;
                    if (gate == 0) g_Z[o] = sigmoidf_(v);
                    else if (gate == 1) g_hr[o] = haux[o] * sigmoidf_(v);
                    else g_XH[o] = v;
                } else if (EPI == 1) {
                    size_t o = (size_t)row * 256 + cc;
                    float ht = tanhf(g_XH[o] + v);
                    float z = g_Z[o];
                    dout[o] = z * haux[o] + (1.f - z) * ht;
                } else {
                    dout[(size_t)row * NC + cc] = v;
                }
            }
        }
    }
}

// ---------------- host launch ----------------
extern "C" void kernel_launch(void* const* d_in, const int* in_sizes, int n_in,
                              void* d_out, int out_size) {
    const float* x   = (const float*)d_in[0];
    const float* h   = (const float*)d_in[1];
    const int*   ei  = (const int*)d_in[2];
    const float* ew  = (const float*)d_in[3];
    const float* Wxz = (const float*)d_in[4];
    const float* bxz = (const float*)d_in[5];
    const float* Whz = (const float*)d_in[6];
    const float* bhz = (const float*)d_in[7];
    const float* Wxr = (const float*)d_in[8];
    const float* bxr = (const float*)d_in[9];
    const float* Whr = (const float*)d_in[10];
    const float* bhr = (const float*)d_in[11];
    const float* Wxh = (const float*)d_in[12];
    const float* bxh = (const float*)d_in[13];
    const float* Whh = (const float*)d_in[14];
    const float* bhh = (const float*)d_in[15];
    const float* Wl  = (const float*)d_in[16];
    const float* bl  = (const float*)d_in[17];

    int M = in_sizes[0] / HID;   // 20000
    int E = in_sizes[3];         // 320000

    float* outp = (float*)d_out;                  // [M,128]
    float* h0   = outp + (size_t)M * 128;         // [M,256]

    void *pLx, *pLh, *pLhr, *pHr, *pB1T, *pb1, *pB2T, *pWlT;
    cudaGetSymbolAddress(&pLx, g_Lx);
    cudaGetSymbolAddress(&pLh, g_Lh);
    cudaGetSymbolAddress(&pLhr, g_Lhr);
    cudaGetSymbolAddress(&pHr, g_hr);
    cudaGetSymbolAddress(&pB1T, g_B1T);
    cudaGetSymbolAddress(&pb1, g_bias1);
    cudaGetSymbolAddress(&pB2T, g_B2T);
    cudaGetSymbolAddress(&pWlT, g_WlT);

    int eb = (E + 255) / 256;
    int nb = (M + 255) / 256;
    int rb = (M + BM - 1) / BM;

    // graph preprocessing (CSR by dst)
    zero_kernel<<<nb, 256>>>(M);
    deg_kernel<<<eb, 256>>>(ei, ew, E);
    norm_count_kernel<<<eb, 256>>>(ei, ew, E);
    scan_kernel<<<1, 1024>>>(M);
    scatter_kernel<<<eb, 256>>>(ei, E);

    // weight packing
    pack1_kernel<<<(768 * 1024 + 255) / 256, 256>>>(Wxz, Whz, Wxr, Whr, Wxh,
                                                    bxz, bhz, bxr, bhr, bxh);
    pack2_kernel<<<(256 * 512 + 255) / 256, 256>>>(Whh);
    pack3_kernel<<<(128 * 256 + 255) / 256, 256>>>(Wl);

    // Lx, Lh
    lap_dual_kernel<<<M, 128>>>(x, h);

    // GEMM1: [x|Lx|h|Lh] @ B1 -> Z, hr, XH (fused gates)
    mm_gemm<4, 0, false><<<dim3(6, rb), 256>>>(
        x, (const float*)pLx, h, (const float*)pLh,
        (const uint32_t*)pB1T, (const float*)pb1, M, 768, h, nullptr);

    // Lhr = L @ hr
    lap_single_kernel<<<M, 64>>>();

    // GEMM2: [hr|Lhr] @ Whh -> h0 (fused tanh + GRU blend)
    mm_gemm<2, 1, false><<<dim3(2, rb), 256>>>(
        (const float*)pHr, (const float*)pLhr, nullptr, nullptr,
        (const uint32_t*)pB2T, bhh, M, 256, h, h0);

    // GEMM3: relu(h0) @ Wl + bl -> out
    mm_gemm<1, 2, true><<<dim3(1, rb), 256>>>(
        h0, nullptr, nullptr, nullptr,
        (const uint32_t*)pWlT, bl, M, 128, nullptr, outp);
}